// round 4
// baseline (speedup 1.0000x reference)
#include <cuda_runtime.h>
#include <cuda_bf16.h>

// Problem constants (fixed by setup_inputs)
#define B_ 64
#define N_ 1024
#define E_ 16384
#define D_ 1024
#define C_ 128

// ---------------- device scratch (static, no allocations) ----------------
__device__ int   g_src[E_], g_dst[E_];
__device__ int   g_deg[N_];
__device__ float g_degf[N_];
__device__ int   g_rowptr[N_ + 1];
__device__ int   g_col[E_];
__device__ int   g_flag2[N_], g_flag3[N_];
__device__ int   g_pos2[N_],  g_pos3[N_];
__device__ int   g_list2[N_], g_list3[N_];
__device__ int   g_c2, g_c3;
__device__ int   g_is64;
__device__ float g_w0[B_ * C_];                 // (h0 @ W_conv) per batch
__device__ float g_pre2[B_ * N_ * C_];          // worst-case frontier buffers
__device__ float g_H2  [B_ * N_ * C_];
__device__ float g_pre3[B_ * N_ * C_];
__device__ float g_H3  [B_ * N_ * C_];

// ---------------- dtype detection: int64 vs int32 edge_index ----------------
// If data is int64, every odd 32-bit word (high half) is 0 (values < 1024).
// If int32, the first 256 odd words are edge values (virtually never all 0).
__global__ void k_detect(const unsigned* ew) {
    __shared__ int any;
    if (threadIdx.x == 0) any = 0;
    __syncthreads();
    if (ew[2 * threadIdx.x + 1] != 0u) atomicOr(&any, 1);
    __syncthreads();
    if (threadIdx.x == 0) g_is64 = any ? 0 : 1;
}

// convert edges to int32 src/dst; also clear per-node scratch
__global__ void k_convert(const void* ew) {
    int i = blockIdx.x * blockDim.x + threadIdx.x;
    if (i < E_) {
        if (g_is64) {
            const long long* p = (const long long*)ew;
            g_src[i] = (int)p[i];
            g_dst[i] = (int)p[E_ + i];
        } else {
            const int* p = (const int*)ew;
            g_src[i] = p[i];
            g_dst[i] = p[E_ + i];
        }
    }
    if (i < N_) { g_deg[i] = 0; g_flag2[i] = 0; g_flag3[i] = 0; }
}

// in-degree + level-3 frontier (srcs of edges into node 0)
__global__ void k_deg(void) {
    int e = blockIdx.x * blockDim.x + threadIdx.x;
    if (e >= E_) return;
    atomicAdd(&g_deg[g_dst[e]], 1);
    if (g_dst[e] == 0) g_flag3[g_src[e]] = 1;
}

// level-2 frontier: srcs of edges into level-3 nodes
__global__ void k_flag2(void) {
    int e = blockIdx.x * blockDim.x + threadIdx.x;
    if (e >= E_) return;
    if (g_flag3[g_dst[e]]) g_flag2[g_src[e]] = 1;
}

// single-block scans: rowptr (CSR), compaction of the two frontiers
__global__ void k_scan(void) {
    __shared__ int s[N_];
    int t = threadIdx.x;

    int d0 = g_deg[t];
    g_degf[t] = (float)d0;
    s[t] = d0;
    __syncthreads();
    for (int off = 1; off < N_; off <<= 1) {
        int v = (t >= off) ? s[t - off] : 0;
        __syncthreads();
        s[t] += v;
        __syncthreads();
    }
    if (t == 0) g_rowptr[0] = 0;
    g_rowptr[t + 1] = s[t];
    __syncthreads();

    int f2 = g_flag2[t];
    s[t] = f2;
    __syncthreads();
    for (int off = 1; off < N_; off <<= 1) {
        int v = (t >= off) ? s[t - off] : 0;
        __syncthreads();
        s[t] += v;
        __syncthreads();
    }
    g_pos2[t] = s[t] - f2;
    if (f2) g_list2[s[t] - f2] = t;
    if (t == N_ - 1) g_c2 = s[t];
    __syncthreads();

    int f3 = g_flag3[t];
    s[t] = f3;
    __syncthreads();
    for (int off = 1; off < N_; off <<= 1) {
        int v = (t >= off) ? s[t - off] : 0;
        __syncthreads();
        s[t] += v;
        __syncthreads();
    }
    g_pos3[t] = s[t] - f3;
    if (f3) g_list3[s[t] - f3] = t;
    if (t == N_ - 1) g_c3 = s[t];
}

// deterministic CSR fill (ballot stream, preserves edge order) — only for
// nodes we will actually aggregate at (frontiers + node 0)
__global__ void k_csrfill(void) {
    int warp = (blockIdx.x * blockDim.x + threadIdx.x) >> 5;
    int lane = threadIdx.x & 31;
    if (warp >= N_) return;
    int n = warp;
    if (!(g_flag2[n] | g_flag3[n] | (n == 0))) return;
    int base = g_rowptr[n], cnt = 0;
    for (int e0 = 0; e0 < E_; e0 += 32) {
        int e = e0 + lane;
        int d = g_dst[e];
        bool m = (d == n);
        unsigned mask = __ballot_sync(0xffffffffu, m);
        if (m) g_col[base + cnt + __popc(mask & ((1u << lane) - 1u))] = g_src[e];
        cnt += __popc(mask);
    }
}

// embedding: h0[b] = relu(x[b] @ W_emb + b_emb);  w0[b] = h0[b] @ W_conv
__global__ void k_emb(const float* __restrict__ x, const float* __restrict__ W_emb,
                      const float* __restrict__ b_emb, const float* __restrict__ W_conv) {
    __shared__ float xs[D_];
    __shared__ float h0s[C_];
    int b = blockIdx.x, c = threadIdx.x;
    for (int d = c; d < D_; d += C_) xs[d] = x[b * D_ + d];
    __syncthreads();
    float acc = b_emb[c];
#pragma unroll 8
    for (int d = 0; d < D_; d++) acc += xs[d] * W_emb[d * C_ + c];
    h0s[c] = fmaxf(acc, 0.f);
    __syncthreads();
    float a2 = 0.f;
#pragma unroll 8
    for (int k = 0; k < C_; k++) a2 += h0s[k] * W_conv[k * C_ + c];
    g_w0[b * C_ + c] = a2;
}

// conv2 pre-aggregation over level-2 frontier.
// H1[b,src,c] = relu(deg[src]*w0[b,c] + bc[c]) computed on the fly (conv1 is analytic).
__global__ void k_pre2(const float* __restrict__ b_conv) {
    int c = threadIdx.x;
    float bc = b_conv[c];
    int c2 = g_c2;
    for (int i = blockIdx.x; i < c2; i += gridDim.x) {
        int n  = g_list2[i];
        int s0 = g_rowptr[n], s1 = g_rowptr[n + 1];
        for (int b = 0; b < B_; b++) {
            float wb  = g_w0[b * C_ + c];
            float acc = 0.f;
            for (int t = s0; t < s1; t++) {
                float ds = g_degf[g_col[t]];
                acc += fmaxf(ds * wb + bc, 0.f);
            }
            g_pre2[(b * N_ + i) * C_ + c] = acc;
        }
    }
}

// conv3 pre-aggregation: sum H2 rows into level-3 frontier nodes
__global__ void k_pre3(void) {
    int c = threadIdx.x;
    int c3 = g_c3;
    for (int j = blockIdx.x; j < c3; j += gridDim.x) {
        int n  = g_list3[j];
        int s0 = g_rowptr[n], s1 = g_rowptr[n + 1];
        for (int b = 0; b < B_; b++) {
            float acc = 0.f;
            for (int t = s0; t < s1; t++) {
                int p = g_pos2[g_col[t]];
                acc += g_H2[(b * N_ + p) * C_ + c];
            }
            g_pre3[(b * N_ + j) * C_ + c] = acc;
        }
    }
}

// frontier GEMM + bias + relu:  out[b,i,:] = relu(in[b,i,:] @ W_conv + b_conv)
// sel==2: pre2->H2 over c2 rows/batch; sel==3: pre3->H3 over c3 rows/batch.
__global__ void k_gemm(int sel, const float* __restrict__ W_conv,
                       const float* __restrict__ b_conv) {
    const float* in  = (sel == 2) ? g_pre2 : g_pre3;
    float*       out = (sel == 2) ? g_H2   : g_H3;
    int cnt = (sel == 2) ? g_c2 : g_c3;
    int M = B_ * cnt;
    __shared__ float As[8][C_];
    int c = threadIdx.x;
    float bc = b_conv[c];
    for (int tile = blockIdx.x; tile * 8 < M; tile += gridDim.x) {
        int r0 = tile * 8;
        int rows = M - r0; if (rows > 8) rows = 8;
        for (int r = 0; r < rows; r++) {
            int rr = r0 + r; int b = rr / cnt, i = rr - b * cnt;
            As[r][c] = in[(b * N_ + i) * C_ + c];
        }
        __syncthreads();
        float acc[8] = {0.f, 0.f, 0.f, 0.f, 0.f, 0.f, 0.f, 0.f};
#pragma unroll 4
        for (int k = 0; k < C_; k++) {
            float w = W_conv[k * C_ + c];
#pragma unroll
            for (int r = 0; r < 8; r++) acc[r] += As[r][k] * w;
        }
        for (int r = 0; r < rows; r++) {
            int rr = r0 + r; int b = rr / cnt, i = rr - b * cnt;
            out[(b * N_ + i) * C_ + c] = fmaxf(acc[r] + bc, 0.f);
        }
        __syncthreads();
    }
}

// conv4 aggregation (node 0 only) + conv4 GEMM + classifier, fused
__global__ void k_final(const float* __restrict__ W_conv, const float* __restrict__ b_conv,
                        const float* __restrict__ W_cls,  const float* __restrict__ b_cls,
                        float* __restrict__ out) {
    __shared__ float s4[C_];
    __shared__ float red[C_];
    int b = blockIdx.x, c = threadIdx.x;
    int s0 = g_rowptr[0], s1 = g_rowptr[1];
    float acc = 0.f;
    for (int t = s0; t < s1; t++) {
        int p = g_pos3[g_col[t]];
        acc += g_H3[(b * N_ + p) * C_ + c];
    }
    s4[c] = acc;
    __syncthreads();
    float a2 = b_conv[c];
#pragma unroll 8
    for (int k = 0; k < C_; k++) a2 += s4[k] * W_conv[k * C_ + c];
    float h = fmaxf(a2, 0.f);
    red[c] = h * W_cls[c];
    __syncthreads();
    for (int off = 64; off > 0; off >>= 1) {
        if (c < off) red[c] += red[c + off];
        __syncthreads();
    }
    if (c == 0) out[b] = red[0] + b_cls[0];
}

extern "C" void kernel_launch(void* const* d_in, const int* in_sizes, int n_in,
                              void* d_out, int out_size) {
    (void)in_sizes; (void)n_in; (void)out_size;
    const float* x      = (const float*)d_in[0];
    const void*  eidx   = d_in[1];
    const float* W_emb  = (const float*)d_in[2];
    const float* b_emb  = (const float*)d_in[3];
    const float* W_conv = (const float*)d_in[4];
    const float* b_conv = (const float*)d_in[5];
    const float* W_cls  = (const float*)d_in[6];
    const float* b_cls  = (const float*)d_in[7];
    float* out = (float*)d_out;

    k_detect<<<1, 256>>>((const unsigned*)eidx);
    k_convert<<<E_ / 256, 256>>>(eidx);
    k_deg<<<E_ / 256, 256>>>();
    k_flag2<<<E_ / 256, 256>>>();
    k_scan<<<1, N_>>>();
    k_csrfill<<<(N_ * 32) / 128, 128>>>();
    k_emb<<<B_, C_>>>(x, W_emb, b_emb, W_conv);
    k_pre2<<<256, C_>>>(b_conv);
    k_gemm<<<1024, C_>>>(2, W_conv, b_conv);
    k_pre3<<<64, C_>>>();
    k_gemm<<<256, C_>>>(3, W_conv, b_conv);
    k_final<<<B_, C_>>>(W_conv, b_conv, W_cls, b_cls, out);
}

// round 5
// speedup vs baseline: 1.5360x; 1.5360x over previous
#include <cuda_runtime.h>
#include <cuda_bf16.h>

// Problem constants (fixed by setup_inputs)
#define B_ 64
#define N_ 1024
#define E_ 16384
#define D_ 1024
#define C_ 128

// ---------------- device scratch (static, no allocations) ----------------
__device__ int   g_src[E_], g_dst[E_];
__device__ int   g_deg[N_];
__device__ float g_degf[N_];
__device__ int   g_rowptr[N_ + 1];
__device__ int   g_col[E_];
__device__ int   g_flag2[N_], g_flag3[N_];
__device__ int   g_list2[N_], g_list3[N_];
__device__ int   g_c2, g_c3;
__device__ int   g_is64;
__device__ float g_w0[B_ * C_];            // (h0 @ W_conv) per batch
__device__ float g_H2[B_ * N_ * C_];       // node-indexed (only frontier2 rows valid)
__device__ float g_H3[B_ * N_ * C_];       // node-indexed (only frontier3 rows valid)

// ---------------- dtype detection: int64 vs int32 edge_index ----------------
__global__ void k_detect(const unsigned* ew) {
    __shared__ int any;
    if (threadIdx.x == 0) any = 0;
    __syncthreads();
    if (ew[2 * threadIdx.x + 1] != 0u) atomicOr(&any, 1);
    __syncthreads();
    if (threadIdx.x == 0) g_is64 = any ? 0 : 1;
}

// convert edges to int32 src/dst; also clear per-node scratch
__global__ void k_convert(const void* ew) {
    int i = blockIdx.x * blockDim.x + threadIdx.x;
    if (i < E_) {
        if (g_is64) {
            const long long* p = (const long long*)ew;
            g_src[i] = (int)p[i];
            g_dst[i] = (int)p[E_ + i];
        } else {
            const int* p = (const int*)ew;
            g_src[i] = p[i];
            g_dst[i] = p[E_ + i];
        }
    }
    if (i < N_) { g_deg[i] = 0; g_flag2[i] = 0; g_flag3[i] = 0; }
}

// in-degree + level-3 frontier (srcs of edges into node 0)
__global__ void k_deg(void) {
    int e = blockIdx.x * blockDim.x + threadIdx.x;
    if (e >= E_) return;
    atomicAdd(&g_deg[g_dst[e]], 1);
    if (g_dst[e] == 0) g_flag3[g_src[e]] = 1;
}

// level-2 frontier: srcs of edges into level-3 nodes
__global__ void k_flag2(void) {
    int e = blockIdx.x * blockDim.x + threadIdx.x;
    if (e >= E_) return;
    if (g_flag3[g_dst[e]]) g_flag2[g_src[e]] = 1;
}

// single-block scans: rowptr (CSR), compaction of the two frontiers
__global__ void k_scan(void) {
    __shared__ int s[N_];
    int t = threadIdx.x;

    int d0 = g_deg[t];
    g_degf[t] = (float)d0;
    s[t] = d0;
    __syncthreads();
    for (int off = 1; off < N_; off <<= 1) {
        int v = (t >= off) ? s[t - off] : 0;
        __syncthreads();
        s[t] += v;
        __syncthreads();
    }
    if (t == 0) g_rowptr[0] = 0;
    g_rowptr[t + 1] = s[t];
    __syncthreads();

    int f2 = g_flag2[t];
    s[t] = f2;
    __syncthreads();
    for (int off = 1; off < N_; off <<= 1) {
        int v = (t >= off) ? s[t - off] : 0;
        __syncthreads();
        s[t] += v;
        __syncthreads();
    }
    if (f2) g_list2[s[t] - f2] = t;
    if (t == N_ - 1) g_c2 = s[t];
    __syncthreads();

    int f3 = g_flag3[t];
    s[t] = f3;
    __syncthreads();
    for (int off = 1; off < N_; off <<= 1) {
        int v = (t >= off) ? s[t - off] : 0;
        __syncthreads();
        s[t] += v;
        __syncthreads();
    }
    if (f3) g_list3[s[t] - f3] = t;
    if (t == N_ - 1) g_c3 = s[t];
}

// deterministic CSR fill (ballot stream, preserves edge order) — only for
// nodes we will actually aggregate at (frontiers + node 0)
__global__ void k_csrfill(void) {
    int warp = (blockIdx.x * blockDim.x + threadIdx.x) >> 5;
    int lane = threadIdx.x & 31;
    if (warp >= N_) return;
    int n = warp;
    if (!(g_flag2[n] | g_flag3[n] | (n == 0))) return;
    int base = g_rowptr[n], cnt = 0;
    for (int e0 = 0; e0 < E_; e0 += 32) {
        int e = e0 + lane;
        int d = g_dst[e];
        bool m = (d == n);
        unsigned mask = __ballot_sync(0xffffffffu, m);
        if (m) g_col[base + cnt + __popc(mask & ((1u << lane) - 1u))] = g_src[e];
        cnt += __popc(mask);
    }
}

// embedding: h0[b] = relu(x[b] @ W_emb + b_emb);  w0[b] = h0[b] @ W_conv
__global__ void k_emb(const float* __restrict__ x, const float* __restrict__ W_emb,
                      const float* __restrict__ b_emb, const float* __restrict__ W_conv) {
    __shared__ __align__(16) float xs[D_];
    __shared__ float h0s[C_];
    int b = blockIdx.x, c = threadIdx.x;
    for (int d = c; d < D_; d += C_) xs[d] = x[b * D_ + d];
    __syncthreads();
    float a0 = b_emb[c], a1 = 0.f;
#pragma unroll 4
    for (int d = 0; d < D_; d += 4) {
        float4 xv = *(const float4*)&xs[d];
        a0 += xv.x * W_emb[(d + 0) * C_ + c];
        a1 += xv.y * W_emb[(d + 1) * C_ + c];
        a0 += xv.z * W_emb[(d + 2) * C_ + c];
        a1 += xv.w * W_emb[(d + 3) * C_ + c];
    }
    h0s[c] = fmaxf(a0 + a1, 0.f);
    __syncthreads();
    float a2 = 0.f;
#pragma unroll 8
    for (int k = 0; k < C_; k++) a2 += h0s[k] * W_conv[k * C_ + c];
    g_w0[b * C_ + c] = a2;
}

// ---- conv2: fused pre-aggregation (analytic conv1) + GEMM + bias + relu ----
// Row rr = b*c2 + i: agg[c] = sum_t relu(deg[col[t]]*w0[b,c] + bc[c])  (t-ordered)
// Then H2[b, list2[i], :] = relu(agg @ W_conv + bc)
__global__ void k_gemm2(const float* __restrict__ W_conv, const float* __restrict__ b_conv) {
    __shared__ __align__(16) float As[8][C_];
    int c = threadIdx.x;
    int cnt = g_c2;
    int M = B_ * cnt;
    float bc = b_conv[c];
    for (int tile = blockIdx.x; tile * 8 < M; tile += gridDim.x) {
        int r0 = tile * 8;
        int rows = M - r0; if (rows > 8) rows = 8;
        for (int r = 0; r < rows; r++) {
            int rr = r0 + r; int b = rr / cnt, i = rr - b * cnt;
            int n = g_list2[i];
            int s0 = g_rowptr[n], s1 = g_rowptr[n + 1];
            float wb = g_w0[b * C_ + c];
            float acc = 0.f;
#pragma unroll 4
            for (int t = s0; t < s1; t++)
                acc += fmaxf(g_degf[g_col[t]] * wb + bc, 0.f);
            As[r][c] = acc;
        }
        __syncthreads();
        float acc[8] = {0.f, 0.f, 0.f, 0.f, 0.f, 0.f, 0.f, 0.f};
#pragma unroll 8
        for (int k = 0; k < C_; k += 4) {
            float w0 = W_conv[(k + 0) * C_ + c];
            float w1 = W_conv[(k + 1) * C_ + c];
            float w2 = W_conv[(k + 2) * C_ + c];
            float w3 = W_conv[(k + 3) * C_ + c];
#pragma unroll
            for (int r = 0; r < 8; r++) {
                float4 a = *(const float4*)&As[r][k];
                acc[r] += a.x * w0; acc[r] += a.y * w1;
                acc[r] += a.z * w2; acc[r] += a.w * w3;
            }
        }
        for (int r = 0; r < rows; r++) {
            int rr = r0 + r; int b = rr / cnt, i = rr - b * cnt;
            g_H2[(b * N_ + g_list2[i]) * C_ + c] = fmaxf(acc[r] + bc, 0.f);
        }
        __syncthreads();
    }
}

// ---- conv3: fused aggregation of H2 rows + GEMM + bias + relu ----
__global__ void k_gemm3(const float* __restrict__ W_conv, const float* __restrict__ b_conv) {
    __shared__ __align__(16) float As[8][C_];
    int c = threadIdx.x;
    int cnt = g_c3;
    int M = B_ * cnt;
    float bc = b_conv[c];
    for (int tile = blockIdx.x; tile * 8 < M; tile += gridDim.x) {
        int r0 = tile * 8;
        int rows = M - r0; if (rows > 8) rows = 8;
        for (int r = 0; r < rows; r++) {
            int rr = r0 + r; int b = rr / cnt, i = rr - b * cnt;
            int n = g_list3[i];
            int s0 = g_rowptr[n], s1 = g_rowptr[n + 1];
            float acc = 0.f;
#pragma unroll 4
            for (int t = s0; t < s1; t++)
                acc += g_H2[(b * N_ + g_col[t]) * C_ + c];
            As[r][c] = acc;
        }
        __syncthreads();
        float acc[8] = {0.f, 0.f, 0.f, 0.f, 0.f, 0.f, 0.f, 0.f};
#pragma unroll 8
        for (int k = 0; k < C_; k += 4) {
            float w0 = W_conv[(k + 0) * C_ + c];
            float w1 = W_conv[(k + 1) * C_ + c];
            float w2 = W_conv[(k + 2) * C_ + c];
            float w3 = W_conv[(k + 3) * C_ + c];
#pragma unroll
            for (int r = 0; r < 8; r++) {
                float4 a = *(const float4*)&As[r][k];
                acc[r] += a.x * w0; acc[r] += a.y * w1;
                acc[r] += a.z * w2; acc[r] += a.w * w3;
            }
        }
        for (int r = 0; r < rows; r++) {
            int rr = r0 + r; int b = rr / cnt, i = rr - b * cnt;
            g_H3[(b * N_ + g_list3[i]) * C_ + c] = fmaxf(acc[r] + bc, 0.f);
        }
        __syncthreads();
    }
}

// conv4 aggregation (node 0 only) + conv4 GEMM + classifier, fused
__global__ void k_final(const float* __restrict__ W_conv, const float* __restrict__ b_conv,
                        const float* __restrict__ W_cls,  const float* __restrict__ b_cls,
                        float* __restrict__ out) {
    __shared__ float s4[C_];
    __shared__ float red[C_];
    int b = blockIdx.x, c = threadIdx.x;
    int s0 = g_rowptr[0], s1 = g_rowptr[1];
    float acc = 0.f;
#pragma unroll 4
    for (int t = s0; t < s1; t++)
        acc += g_H3[(b * N_ + g_col[t]) * C_ + c];
    s4[c] = acc;
    __syncthreads();
    float a2 = b_conv[c];
#pragma unroll 8
    for (int k = 0; k < C_; k++) a2 += s4[k] * W_conv[k * C_ + c];
    float h = fmaxf(a2, 0.f);
    red[c] = h * W_cls[c];
    __syncthreads();
    for (int off = 64; off > 0; off >>= 1) {
        if (c < off) red[c] += red[c + off];
        __syncthreads();
    }
    if (c == 0) out[b] = red[0] + b_cls[0];
}

extern "C" void kernel_launch(void* const* d_in, const int* in_sizes, int n_in,
                              void* d_out, int out_size) {
    (void)in_sizes; (void)n_in; (void)out_size;
    const float* x      = (const float*)d_in[0];
    const void*  eidx   = d_in[1];
    const float* W_emb  = (const float*)d_in[2];
    const float* b_emb  = (const float*)d_in[3];
    const float* W_conv = (const float*)d_in[4];
    const float* b_conv = (const float*)d_in[5];
    const float* W_cls  = (const float*)d_in[6];
    const float* b_cls  = (const float*)d_in[7];
    float* out = (float*)d_out;

    k_detect<<<1, 256>>>((const unsigned*)eidx);
    k_convert<<<E_ / 256, 256>>>(eidx);
    k_deg<<<E_ / 256, 256>>>();
    k_flag2<<<E_ / 256, 256>>>();
    k_scan<<<1, N_>>>();
    k_csrfill<<<(N_ * 32) / 128, 128>>>();
    k_emb<<<B_, C_>>>(x, W_emb, b_emb, W_conv);
    k_gemm2<<<1024, C_>>>(W_conv, b_conv);
    k_gemm3<<<256, C_>>>(W_conv, b_conv);
    k_final<<<B_, C_>>>(W_conv, b_conv, W_cls, b_cls, out);
}